// round 4
// baseline (speedup 1.0000x reference)
#include <cuda_runtime.h>
#include <cstdint>
#include <cstddef>

#define DEVI __device__ __forceinline__

constexpr int Bsz = 8192;
constexpr int Csz = 256;
constexpr int NBl = 8;
constexpr int BM = 32, BN = 64, BK = 8, TN = 4;

// ---- scratch (device globals; no allocs allowed) ----
__device__ float g_h [Bsz * Csz * NBl];
__device__ float g_xr[Bsz * Csz * NBl];
__device__ float g_lf[Bsz * Csz * NBl];
__device__ float g_t0[Bsz * Csz * NBl];

// ---- algebra tables (grade-ordered blades: [1, e1,e2,e3, e12,e13,e23, e123]) ----
__device__ constexpr int ORD [8] = {0, 1, 2, 4, 3, 5, 6, 7};  // idx -> bitmask
__device__ constexpr int IDXM[8] = {0, 1, 2, 4, 3, 5, 6, 7};  // bitmask -> idx
__device__ constexpr int GRc [8] = {0, 1, 1, 1, 2, 2, 2, 3};  // idx -> grade
// sign of blade product by bitmask: bit mb of NEGM[ma] set => negative
__device__ constexpr unsigned NEGM[8] = {0x00u, 0x00u, 0xAAu, 0xAAu,
                                         0x66u, 0x66u, 0xCCu, 0xCCu};
// lexicographic rank of the 20 valid (gi,gj,gk) grade paths (np.argwhere order)
__device__ constexpr signed char PATHT[4][4][4] = {
  { { 0,-1,-1,-1}, {-1, 1,-1,-1}, {-1,-1, 2,-1}, {-1,-1,-1, 3} },
  { {-1, 4,-1,-1}, { 5,-1, 6,-1}, {-1, 7,-1, 8}, {-1,-1, 9,-1} },
  { {-1,-1,10,-1}, {-1,11,-1,12}, {13,-1,14,-1}, {-1,15,-1,-1} },
  { {-1,-1,-1,16}, {-1,-1,17,-1}, {-1,18,-1,-1}, {19,-1,-1,-1} }
};

// ---- packed f32x2 helpers (b64 operands: "l" constraints, NOT "d") ----
DEVI double dfma2(double a, double b, double c) {
    unsigned long long ra = __double_as_longlong(a);
    unsigned long long rb = __double_as_longlong(b);
    unsigned long long rc = __double_as_longlong(c);
    unsigned long long rd;
    asm("fma.rn.f32x2 %0, %1, %2, %3;" : "=l"(rd) : "l"(ra), "l"(rb), "l"(rc));
    return __longlong_as_double(rd);
}
DEVI double pk2(float v) { return __hiloint2double(__float_as_int(v), __float_as_int(v)); }
DEVI float lo2(double d) { return __int_as_float(__double2loint(d)); }
DEVI float hi2(double d) { return __int_as_float(__double2hiint(d)); }
DEVI float sigm(float x) { return 1.0f / (1.0f + __expf(-x)); }

// ---- fused blade-GEMM + epilogue ----
// y[b,o,k] = sum_i x[b,i,k] * w[o,i,grade(k)]   x:[B,C,8]  w:[C,C,4]
// EPI 0: +bias(scalar), mv_silu(pa,pb) | EPI 1: grade_norm(pa) | EPI 2: +bias(scalar)
template <int EPI>
__global__ void __launch_bounds__(256, 2)
gemm_epi(const float* __restrict__ X, const float* __restrict__ W,
         const float* __restrict__ bias, const float* __restrict__ pa,
         const float* __restrict__ pb, float* __restrict__ Y)
{
    __shared__ __align__(16) float  Xs[BK][NBl][BM + 2]; // [k][blade][b], pad 2
    __shared__ __align__(16) double Wsd[BK][BN][4];      // weights pre-broadcast f32x2

    const int tid  = threadIdx.x;
    const int tx   = tid >> 4;        // 0..15 out-channel group (TN=4)
    const int ty   = tid & 15;        // 0..15 batch-pair (2 rows packed)
    const int row0 = blockIdx.x * BM;
    const int col0 = blockIdx.y * BN;

    double acc[TN][NBl];
#pragma unroll
    for (int t = 0; t < TN; t++)
#pragma unroll
        for (int k = 0; k < NBl; k++) acc[t][k] = 0.0;

    const int lb  = tid >> 3;         // 0..31 x-row
    const int li  = tid & 7;          // 0..7  x-k
    const int lo_ = tid >> 2;         // 0..63 w-row
    const int lp  = (tid & 3) * 2;    // 0,2,4,6 w-k pair

    const float* xg = X + ((size_t)(row0 + lb) * Csz + li) * NBl;
    const float* wg = W + ((size_t)(col0 + lo_) * Csz + lp) * 4;

    for (int kk = 0; kk < Csz; kk += BK) {
        const float4 xa  = *(const float4*)(xg + (size_t)kk * NBl);
        const float4 xb  = *(const float4*)(xg + (size_t)kk * NBl + 4);
        const float4 wa  = *(const float4*)(wg + (size_t)kk * 4);
        const float4 wbv = *(const float4*)(wg + (size_t)kk * 4 + 4);

        Xs[li][0][lb] = xa.x;  Xs[li][1][lb] = xa.y;
        Xs[li][2][lb] = xa.z;  Xs[li][3][lb] = xa.w;
        Xs[li][4][lb] = xb.x;  Xs[li][5][lb] = xb.y;
        Xs[li][6][lb] = xb.z;  Xs[li][7][lb] = xb.w;

        Wsd[lp  ][lo_][0] = pk2(wa.x);  Wsd[lp  ][lo_][1] = pk2(wa.y);
        Wsd[lp  ][lo_][2] = pk2(wa.z);  Wsd[lp  ][lo_][3] = pk2(wa.w);
        Wsd[lp+1][lo_][0] = pk2(wbv.x); Wsd[lp+1][lo_][1] = pk2(wbv.y);
        Wsd[lp+1][lo_][2] = pk2(wbv.z); Wsd[lp+1][lo_][3] = pk2(wbv.w);

        __syncthreads();
#pragma unroll
        for (int i = 0; i < BK; i++) {
            double xk[NBl];
#pragma unroll
            for (int k = 0; k < NBl; k++)
                xk[k] = *(const double*)(&Xs[i][k][ty * 2]);
#pragma unroll
            for (int t = 0; t < TN; t++) {
                const double2 wp0 = *(const double2*)(&Wsd[i][tx * TN + t][0]);
                const double2 wp1 = *(const double2*)(&Wsd[i][tx * TN + t][2]);
                acc[t][0] = dfma2(xk[0], wp0.x, acc[t][0]);
                acc[t][1] = dfma2(xk[1], wp0.y, acc[t][1]);
                acc[t][2] = dfma2(xk[2], wp0.y, acc[t][2]);
                acc[t][3] = dfma2(xk[3], wp0.y, acc[t][3]);
                acc[t][4] = dfma2(xk[4], wp1.x, acc[t][4]);
                acc[t][5] = dfma2(xk[5], wp1.x, acc[t][5]);
                acc[t][6] = dfma2(xk[6], wp1.x, acc[t][6]);
                acc[t][7] = dfma2(xk[7], wp1.y, acc[t][7]);
            }
        }
        __syncthreads();
    }

    const int bb = row0 + ty * 2;
#pragma unroll
    for (int t = 0; t < TN; t++) {
        const int o = col0 + tx * TN + t;
        float yr[2][NBl];
#pragma unroll
        for (int k = 0; k < NBl; k++) { yr[0][k] = lo2(acc[t][k]); yr[1][k] = hi2(acc[t][k]); }
#pragma unroll
        for (int r = 0; r < 2; r++) {
            float* y = yr[r];
            if constexpr (EPI == 0) {
                y[0] += bias[o];
                const float i0 = y[0];
                const float i1 = y[1]*y[1] + y[2]*y[2] + y[3]*y[3];
                const float i2 = y[4]*y[4] + y[5]*y[5] + y[6]*y[6];
                const float i3 = y[7]*y[7];
                const float gg0 = sigm(pa[o*4+0] * i0 + pb[o*4+0]);
                const float gg1 = sigm(pa[o*4+1] * i1 + pb[o*4+1]);
                const float gg2 = sigm(pa[o*4+2] * i2 + pb[o*4+2]);
                const float gg3 = sigm(pa[o*4+3] * i3 + pb[o*4+3]);
                y[0]*=gg0; y[1]*=gg1; y[2]*=gg1; y[3]*=gg1;
                y[4]*=gg2; y[5]*=gg2; y[6]*=gg2; y[7]*=gg3;
            } else if constexpr (EPI == 1) {
                const float n0 = fabsf(y[0]);
                const float n1 = sqrtf(y[1]*y[1] + y[2]*y[2] + y[3]*y[3]);
                const float n2 = sqrtf(y[4]*y[4] + y[5]*y[5] + y[6]*y[6]);
                const float n3 = fabsf(y[7]);
                const float r0 = 1.0f / (fmaf(sigm(pa[o*4+0]), n0 - 1.0f, 1.0f) + 1e-6f);
                const float r1 = 1.0f / (fmaf(sigm(pa[o*4+1]), n1 - 1.0f, 1.0f) + 1e-6f);
                const float r2 = 1.0f / (fmaf(sigm(pa[o*4+2]), n2 - 1.0f, 1.0f) + 1e-6f);
                const float r3 = 1.0f / (fmaf(sigm(pa[o*4+3]), n3 - 1.0f, 1.0f) + 1e-6f);
                y[0]*=r0; y[1]*=r1; y[2]*=r1; y[3]*=r1;
                y[4]*=r2; y[5]*=r2; y[6]*=r2; y[7]*=r3;
            } else {
                y[0] += bias[o];
            }
            float4* dst = (float4*)(Y + ((size_t)(bb + r) * Csz + o) * NBl);
            dst[0] = make_float4(y[0], y[1], y[2], y[3]);
            dst[1] = make_float4(y[4], y[5], y[6], y[7]);
        }
    }
}

// ---- fused geometric product + multivector layernorm ----
__global__ void __launch_bounds__(256, 4)
gp_ln(const float* __restrict__ Xh, const float* __restrict__ XR,
      const float* __restrict__ Lf, const float* __restrict__ GPW,
      const float* __restrict__ LNA, float* __restrict__ Y)
{
    const int b = blockIdx.x, c = threadIdx.x;
    const size_t base = ((size_t)b * Csz + c) * NBl;

    float xv[8], rv[8], lv[8];
    {
        const float4 a0 = *(const float4*)(Xh + base);
        const float4 a1 = *(const float4*)(Xh + base + 4);
        xv[0]=a0.x; xv[1]=a0.y; xv[2]=a0.z; xv[3]=a0.w;
        xv[4]=a1.x; xv[5]=a1.y; xv[6]=a1.z; xv[7]=a1.w;
        const float4 b0 = *(const float4*)(XR + base);
        const float4 b1 = *(const float4*)(XR + base + 4);
        rv[0]=b0.x; rv[1]=b0.y; rv[2]=b0.z; rv[3]=b0.w;
        rv[4]=b1.x; rv[5]=b1.y; rv[6]=b1.z; rv[7]=b1.w;
        const float4 c0 = *(const float4*)(Lf + base);
        const float4 c1 = *(const float4*)(Lf + base + 4);
        lv[0]=c0.x; lv[1]=c0.y; lv[2]=c0.z; lv[3]=c0.w;
        lv[4]=c1.x; lv[5]=c1.y; lv[6]=c1.z; lv[7]=c1.w;
    }
    float w20[20];
    {
        const float* wp = GPW + c * 20;
#pragma unroll
        for (int q = 0; q < 5; q++) *(float4*)&w20[q*4] = *(const float4*)(wp + q*4);
    }

    float gp[8] = {0,0,0,0,0,0,0,0};
#pragma unroll
    for (int i = 0; i < 8; i++) {
#pragma unroll
        for (int j = 0; j < 8; j++) {
            const int ma = ORD[i], mb = ORD[j];
            const int ko = IDXM[ma ^ mb];
            const int p  = PATHT[GRc[i]][GRc[j]][GRc[ko]];
            const bool neg = (NEGM[ma] >> mb) & 1;
            const float wv = neg ? -w20[p] : w20[p];
            gp[ko] = fmaf(wv, xv[i] * rv[j], gp[ko]);
        }
    }

    float s[8], sq = 0.0f;
#pragma unroll
    for (int k = 0; k < 8; k++) {
        s[k] = (lv[k] + gp[k]) * 0.70710678118654752f;
        sq = fmaf(s[k], s[k], sq);
    }
    float v = sqrtf(sq);

    __shared__ float red[8];
#pragma unroll
    for (int off = 16; off; off >>= 1) v += __shfl_xor_sync(0xffffffffu, v, off);
    if ((c & 31) == 0) red[c >> 5] = v;
    __syncthreads();
    const float tot = red[0]+red[1]+red[2]+red[3]+red[4]+red[5]+red[6]+red[7];
    const float scale = LNA[c] / (tot * (1.0f / 256.0f) + 1e-6f);

    float4* dst = (float4*)(Y + base);
    dst[0] = make_float4(s[0]*scale, s[1]*scale, s[2]*scale, s[3]*scale);
    dst[1] = make_float4(s[4]*scale, s[5]*scale, s[6]*scale, s[7]*scale);
}

// ---- launch ----
static void run_layer(const float* in, const float* const* P, float* out,
                      float* h, float* xr, float* lf)
{
    // P: [w_lin, b_lin, silu_a, silu_b, w_right, w_left, b_left, norm_a, gp_w, ln_a]
    dim3 gg(Bsz / BM, Csz / BN);
    gemm_epi<0><<<gg, 256>>>(in, P[0], P[1], P[2], P[3], h);
    gemm_epi<1><<<gg, 256>>>(h,  P[4], nullptr, P[7], nullptr, xr);
    gemm_epi<2><<<gg, 256>>>(h,  P[5], P[6], nullptr, nullptr, lf);
    gp_ln<<<Bsz, 256>>>(h, xr, lf, P[8], P[9], out);
}

extern "C" void kernel_launch(void* const* d_in, const int* in_sizes, int n_in,
                              void* d_out, int out_size)
{
    (void)in_sizes; (void)n_in; (void)out_size;
    const float* x = (const float*)d_in[0];
    float* out = (float*)d_out;

    float *h, *xr, *lf, *t0;
    cudaGetSymbolAddress((void**)&h,  g_h);
    cudaGetSymbolAddress((void**)&xr, g_xr);
    cudaGetSymbolAddress((void**)&lf, g_lf);
    cudaGetSymbolAddress((void**)&t0, g_t0);

    const float* P0[10];
    const float* P1[10];
    for (int i = 0; i < 10; i++) { P0[i] = (const float*)d_in[1 + i];
                                   P1[i] = (const float*)d_in[11 + i]; }

    run_layer(x,  P0, t0,  h, xr, lf);
    run_layer(t0, P1, out, h, xr, lf);
}

// round 9
// speedup vs baseline: 3.4170x; 3.4170x over previous
#include <cuda_runtime.h>
#include <cuda_bf16.h>
#include <cstdint>
#include <cstddef>

#define DEVI __device__ __forceinline__
typedef __nv_bfloat16 bf16;

constexpr int Bsz = 8192, Csz = 256, NBl = 8;
constexpr size_t BC = (size_t)Bsz * Csz;   // elems per blade plane

// ---------------- scratch (device globals) ----------------
__device__ float g_raw[NBl * BC];
__device__ float g_hf [NBl * BC];
__device__ float g_xr [NBl * BC];
__device__ float g_lf [NBl * BC];
__device__ bf16  g_inH[NBl * BC];
__device__ bf16  g_inL[NBl * BC];
__device__ bf16  g_hH [NBl * BC];
__device__ bf16  g_hL [NBl * BC];
__device__ bf16  g_wH [4 * Csz * Csz];
__device__ bf16  g_wL [4 * Csz * Csz];

// ---------------- algebra tables ----------------
__device__ constexpr int ORD [8] = {0, 1, 2, 4, 3, 5, 6, 7};
__device__ constexpr int IDXM[8] = {0, 1, 2, 4, 3, 5, 6, 7};
__device__ constexpr int GRc [8] = {0, 1, 1, 1, 2, 2, 2, 3};
__device__ constexpr unsigned NEGM[8] = {0x00u, 0x00u, 0xAAu, 0xAAu,
                                         0x66u, 0x66u, 0xCCu, 0xCCu};
__device__ constexpr signed char PATHT[4][4][4] = {
  { { 0,-1,-1,-1}, {-1, 1,-1,-1}, {-1,-1, 2,-1}, {-1,-1,-1, 3} },
  { {-1, 4,-1,-1}, { 5,-1, 6,-1}, {-1, 7,-1, 8}, {-1,-1, 9,-1} },
  { {-1,-1,10,-1}, {-1,11,-1,12}, {13,-1,14,-1}, {-1,15,-1,-1} },
  { {-1,-1,-1,16}, {-1,-1,17,-1}, {-1,18,-1,-1}, {19,-1,-1,-1} }
};

DEVI float sigm(float x) { return 1.0f / (1.0f + __expf(-x)); }

DEVI uint32_t smem_u32(const void* p) {
    uint32_t a;
    asm("{ .reg .u64 t; cvta.to.shared.u64 t, %1; cvt.u32.u64 %0, t; }" : "=r"(a) : "l"(p));
    return a;
}

// ---- warp MMA primitives (sm_80+, valid on compute_100) ----
DEVI void ldsm_x4(uint32_t& r0, uint32_t& r1, uint32_t& r2, uint32_t& r3, uint32_t addr) {
    asm volatile("ldmatrix.sync.aligned.m8n8.x4.shared.b16 {%0,%1,%2,%3}, [%4];"
                 : "=r"(r0), "=r"(r1), "=r"(r2), "=r"(r3) : "r"(addr));
}
DEVI void mma_bf16(float* c, uint32_t a0, uint32_t a1, uint32_t a2, uint32_t a3,
                   uint32_t b0, uint32_t b1) {
    asm volatile(
        "mma.sync.aligned.m16n8k16.row.col.f32.bf16.bf16.f32 "
        "{%0,%1,%2,%3}, {%4,%5,%6,%7}, {%8,%9}, {%0,%1,%2,%3};"
        : "+f"(c[0]), "+f"(c[1]), "+f"(c[2]), "+f"(c[3])
        : "r"(a0), "r"(a1), "r"(a2), "r"(a3), "r"(b0), "r"(b1));
}

// ---------------- mma.sync blade-plane GEMM ----------------
// OUT[blade][b][o] = sum_i IN[blade][b][i] * W[grade(blade)][o][i]
// 3-term hi/lo split, fp32 accum: AH*WH + AL*WH + AH*WL
constexpr int SKW = 40;   // smem row stride in bf16 (32 data + 8 pad) -> 80B rows
__global__ void __launch_bounds__(256, 2)
gemm_mma(const bf16* __restrict__ AH, const bf16* __restrict__ AL,
         const bf16* __restrict__ WH, const bf16* __restrict__ WL,
         float* __restrict__ OUT)
{
    __shared__ bf16 sAH[128 * SKW], sAL[128 * SKW], sBH[128 * SKW], sBL[128 * SKW];

    const int tid = threadIdx.x, wid = tid >> 5, lane = tid & 31;
    const int blade = blockIdx.z, grade = GRc[blade];
    const int row0 = blockIdx.x * 128, col0 = blockIdx.y * 128;
    const int wm = wid & 1, wn = wid >> 1;     // warp tile: m64 x n32

    const bf16* aH = AH + (size_t)blade * BC + (size_t)row0 * Csz;
    const bf16* aL = AL + (size_t)blade * BC + (size_t)row0 * Csz;
    const bf16* wH = WH + (size_t)grade * Csz * Csz + (size_t)col0 * Csz;
    const bf16* wL = WL + (size_t)grade * Csz * Csz + (size_t)col0 * Csz;

    const uint32_t bAH = smem_u32(sAH), bAL = smem_u32(sAL);
    const uint32_t bBH = smem_u32(sBH), bBL = smem_u32(sBL);

    float acc[4][4][4];
#pragma unroll
    for (int mi = 0; mi < 4; mi++)
#pragma unroll
        for (int ni = 0; ni < 4; ni++)
#pragma unroll
            for (int q = 0; q < 4; q++) acc[mi][ni][q] = 0.0f;

    // per-lane ldmatrix address offsets (bytes), within a k16 step
    const int lq = lane >> 3, lr = lane & 7;
    // A tiles: row = mbase + (lq&1)*8 + lr ; col = k0 + (lq>>1)*8
    const uint32_t offA = (uint32_t)(((lq & 1) * 8 + lr) * SKW + (lq >> 1) * 8) * 2;
    // B tiles: row = nbase + (lq>>1)*8 + lr ; col = k0 + (lq&1)*8
    const uint32_t offB = (uint32_t)(((lq >> 1) * 8 + lr) * SKW + (lq & 1) * 8) * 2;

    for (int ch = 0; ch < 8; ch++) {           // K chunks of 32
        // load 128 rows x 32 cols per array: 512 uint4 each, 2 per thread
#pragma unroll
        for (int it = 0; it < 2; it++) {
            const int t = tid + it * 256;
            const int r = t >> 2, c = t & 3;
            const size_t src = (size_t)r * Csz + ch * 32 + c * 8;
            const int d = r * SKW + c * 8;
            *(uint4*)(sAH + d) = *(const uint4*)(aH + src);
            *(uint4*)(sAL + d) = *(const uint4*)(aL + src);
            *(uint4*)(sBH + d) = *(const uint4*)(wH + src);
            *(uint4*)(sBL + d) = *(const uint4*)(wL + src);
        }
        __syncthreads();

#pragma unroll
        for (int kh = 0; kh < 2; kh++) {
            const uint32_t kb = (uint32_t)(kh * 16) * 2;
            // B fragments: n32 x k16 -> 2 ldmatrix.x4 per precision
            uint32_t bh[4][2], bl[4][2];
#pragma unroll
            for (int nb = 0; nb < 2; nb++) {
                const uint32_t nbase = (uint32_t)((wn * 32 + nb * 16) * SKW) * 2;
                ldsm_x4(bh[nb*2][0], bh[nb*2][1], bh[nb*2+1][0], bh[nb*2+1][1],
                        bBH + nbase + offB + kb);
                ldsm_x4(bl[nb*2][0], bl[nb*2][1], bl[nb*2+1][0], bl[nb*2+1][1],
                        bBL + nbase + offB + kb);
            }
#pragma unroll
            for (int mi = 0; mi < 4; mi++) {
                const uint32_t mbase = (uint32_t)((wm * 64 + mi * 16) * SKW) * 2;
                uint32_t ah0, ah1, ah2, ah3, al0, al1, al2, al3;
                ldsm_x4(ah0, ah1, ah2, ah3, bAH + mbase + offA + kb);
                ldsm_x4(al0, al1, al2, al3, bAL + mbase + offA + kb);
#pragma unroll
                for (int ni = 0; ni < 4; ni++) {
                    mma_bf16(acc[mi][ni], ah0, ah1, ah2, ah3, bh[ni][0], bh[ni][1]);
                    mma_bf16(acc[mi][ni], al0, al1, al2, al3, bh[ni][0], bh[ni][1]);
                    mma_bf16(acc[mi][ni], ah0, ah1, ah2, ah3, bl[ni][0], bl[ni][1]);
                }
            }
        }
        __syncthreads();
    }

    // epilogue: write fp32 planar
    float* outp = OUT + (size_t)blade * BC;
#pragma unroll
    for (int mi = 0; mi < 4; mi++) {
        const int m0 = row0 + wm * 64 + mi * 16 + (lane >> 2);
#pragma unroll
        for (int ni = 0; ni < 4; ni++) {
            const int n = col0 + wn * 32 + ni * 8 + (lane & 3) * 2;
            *(float2*)(outp + (size_t)m0 * Csz + n)       = make_float2(acc[mi][ni][0], acc[mi][ni][1]);
            *(float2*)(outp + (size_t)(m0 + 8) * Csz + n) = make_float2(acc[mi][ni][2], acc[mi][ni][3]);
        }
    }
}

// ---------------- conversions & elementwise passes ----------------
__global__ void conv_x(const float* __restrict__ X, bf16* __restrict__ H, bf16* __restrict__ L) {
    const size_t idx = (size_t)blockIdx.x * 256 + threadIdx.x;
    const float4 a = *(const float4*)(X + idx * 8);
    const float4 b = *(const float4*)(X + idx * 8 + 4);
    const float v[8] = {a.x, a.y, a.z, a.w, b.x, b.y, b.z, b.w};
#pragma unroll
    for (int k = 0; k < 8; k++) {
        const bf16 h = __float2bfloat16(v[k]);
        H[k * BC + idx] = h;
        L[k * BC + idx] = __float2bfloat16(v[k] - __bfloat162float(h));
    }
}

__global__ void conv_w(const float* __restrict__ W, bf16* __restrict__ WH, bf16* __restrict__ WL) {
    const int idx = blockIdx.x * 256 + threadIdx.x;  // o*256+i
    const float4 v = *(const float4*)(W + (size_t)idx * 4);
    const float g[4] = {v.x, v.y, v.z, v.w};
#pragma unroll
    for (int gg = 0; gg < 4; gg++) {
        const bf16 h = __float2bfloat16(g[gg]);
        WH[gg * 65536 + idx] = h;
        WL[gg * 65536 + idx] = __float2bfloat16(g[gg] - __bfloat162float(h));
    }
}

__global__ void silu_pass(const float* __restrict__ RAW, const float* __restrict__ blin,
                          const float* __restrict__ pa, const float* __restrict__ pb,
                          bf16* __restrict__ HH, bf16* __restrict__ HL, float* __restrict__ HF) {
    const size_t idx = (size_t)blockIdx.x * 256 + threadIdx.x;
    const int c = (int)(idx & 255);
    float y[8];
#pragma unroll
    for (int k = 0; k < 8; k++) y[k] = RAW[k * BC + idx];
    y[0] += blin[c];
    const float i0 = y[0];
    const float i1 = y[1]*y[1] + y[2]*y[2] + y[3]*y[3];
    const float i2 = y[4]*y[4] + y[5]*y[5] + y[6]*y[6];
    const float i3 = y[7]*y[7];
    const float g0 = sigm(pa[c*4+0] * i0 + pb[c*4+0]);
    const float g1 = sigm(pa[c*4+1] * i1 + pb[c*4+1]);
    const float g2 = sigm(pa[c*4+2] * i2 + pb[c*4+2]);
    const float g3 = sigm(pa[c*4+3] * i3 + pb[c*4+3]);
    const float gk[8] = {g0, g1, g1, g1, g2, g2, g2, g3};
#pragma unroll
    for (int k = 0; k < 8; k++) {
        const float v = y[k] * gk[k];
        HF[k * BC + idx] = v;
        const bf16 h = __float2bfloat16(v);
        HH[k * BC + idx] = h;
        HL[k * BC + idx] = __float2bfloat16(v - __bfloat162float(h));
    }
}

__global__ void gnorm_pass(const float* __restrict__ RAW, const float* __restrict__ pa,
                           float* __restrict__ XR) {
    const size_t idx = (size_t)blockIdx.x * 256 + threadIdx.x;
    const int c = (int)(idx & 255);
    float y[8];
#pragma unroll
    for (int k = 0; k < 8; k++) y[k] = RAW[k * BC + idx];
    const float n0 = fabsf(y[0]);
    const float n1 = sqrtf(y[1]*y[1] + y[2]*y[2] + y[3]*y[3]);
    const float n2 = sqrtf(y[4]*y[4] + y[5]*y[5] + y[6]*y[6]);
    const float n3 = fabsf(y[7]);
    const float r0 = 1.0f / (fmaf(sigm(pa[c*4+0]), n0 - 1.0f, 1.0f) + 1e-6f);
    const float r1 = 1.0f / (fmaf(sigm(pa[c*4+1]), n1 - 1.0f, 1.0f) + 1e-6f);
    const float r2 = 1.0f / (fmaf(sigm(pa[c*4+2]), n2 - 1.0f, 1.0f) + 1e-6f);
    const float r3 = 1.0f / (fmaf(sigm(pa[c*4+3]), n3 - 1.0f, 1.0f) + 1e-6f);
    const float rk[8] = {r0, r1, r1, r1, r2, r2, r2, r3};
#pragma unroll
    for (int k = 0; k < 8; k++) XR[k * BC + idx] = y[k] * rk[k];
}

// ---------------- fused geometric product + layernorm ----------------
template <int OUTMODE>
__global__ void __launch_bounds__(256, 4)
gp_ln(const float* __restrict__ Xh, const float* __restrict__ XR,
      const float* __restrict__ Lf, const float* __restrict__ GPW,
      const float* __restrict__ LNA, const float* __restrict__ BL,
      float* __restrict__ OutF, bf16* __restrict__ OutH, bf16* __restrict__ OutL)
{
    const int b = blockIdx.x, c = threadIdx.x;
    const size_t idx = (size_t)b * Csz + c;

    float xv[8], rv[8], lv[8];
#pragma unroll
    for (int k = 0; k < 8; k++) {
        xv[k] = Xh[k * BC + idx];
        rv[k] = XR[k * BC + idx];
        lv[k] = Lf[k * BC + idx];
    }
    lv[0] += BL[c];

    float w20[20];
    {
        const float* wp = GPW + c * 20;
#pragma unroll
        for (int q = 0; q < 5; q++) *(float4*)&w20[q*4] = *(const float4*)(wp + q*4);
    }

    float gp[8] = {0,0,0,0,0,0,0,0};
#pragma unroll
    for (int i = 0; i < 8; i++) {
#pragma unroll
        for (int j = 0; j < 8; j++) {
            const int ma = ORD[i], mb = ORD[j];
            const int ko = IDXM[ma ^ mb];
            const int p  = PATHT[GRc[i]][GRc[j]][GRc[ko]];
            const bool neg = (NEGM[ma] >> mb) & 1;
            const float wv = neg ? -w20[p] : w20[p];
            gp[ko] = fmaf(wv, xv[i] * rv[j], gp[ko]);
        }
    }

    float s[8], sq = 0.0f;
#pragma unroll
    for (int k = 0; k < 8; k++) {
        s[k] = (lv[k] + gp[k]) * 0.70710678118654752f;
        sq = fmaf(s[k], s[k], sq);
    }
    float v = sqrtf(sq);

    __shared__ float red[8];
#pragma unroll
    for (int off = 16; off; off >>= 1) v += __shfl_xor_sync(0xffffffffu, v, off);
    if ((c & 31) == 0) red[c >> 5] = v;
    __syncthreads();
    const float tot = red[0]+red[1]+red[2]+red[3]+red[4]+red[5]+red[6]+red[7];
    const float scale = LNA[c] / (tot * (1.0f / 256.0f) + 1e-6f);

    if constexpr (OUTMODE == 0) {
#pragma unroll
        for (int k = 0; k < 8; k++) {
            const float sv = s[k] * scale;
            const bf16 h = __float2bfloat16(sv);
            OutH[k * BC + idx] = h;
            OutL[k * BC + idx] = __float2bfloat16(sv - __bfloat162float(h));
        }
    } else {
        float4* dst = (float4*)(OutF + idx * 8);
        dst[0] = make_float4(s[0]*scale, s[1]*scale, s[2]*scale, s[3]*scale);
        dst[1] = make_float4(s[4]*scale, s[5]*scale, s[6]*scale, s[7]*scale);
    }
}

// ---------------- launch ----------------
extern "C" void kernel_launch(void* const* d_in, const int* in_sizes, int n_in,
                              void* d_out, int out_size)
{
    (void)in_sizes; (void)n_in; (void)out_size;
    const float* x = (const float*)d_in[0];
    float* out = (float*)d_out;

    float *raw, *hf, *xr, *lf;
    bf16 *inH, *inL, *hH, *hL, *wH, *wL;
    cudaGetSymbolAddress((void**)&raw, g_raw);
    cudaGetSymbolAddress((void**)&hf,  g_hf);
    cudaGetSymbolAddress((void**)&xr,  g_xr);
    cudaGetSymbolAddress((void**)&lf,  g_lf);
    cudaGetSymbolAddress((void**)&inH, g_inH);
    cudaGetSymbolAddress((void**)&inL, g_inL);
    cudaGetSymbolAddress((void**)&hH,  g_hH);
    cudaGetSymbolAddress((void**)&hL,  g_hL);
    cudaGetSymbolAddress((void**)&wH,  g_wH);
    cudaGetSymbolAddress((void**)&wL,  g_wL);

    const int EB = (int)(BC / 256);
    const dim3 GG(Bsz / 128, Csz / 128, NBl);   // 64 x 2 x 8

    conv_x<<<EB, 256>>>(x, inH, inL);

    for (int l = 0; l < 2; l++) {
        const float* const* P = (const float* const*)(d_in + 1 + 10 * l);
        // P: [w_lin, b_lin, silu_a, silu_b, w_right, w_left, b_left, norm_a, gp_w, ln_a]
        conv_w<<<256, 256>>>(P[0], wH, wL);
        gemm_mma<<<GG, 256>>>(inH, inL, wH, wL, raw);
        silu_pass<<<EB, 256>>>(raw, P[1], P[2], P[3], hH, hL, hf);

        conv_w<<<256, 256>>>(P[4], wH, wL);
        gemm_mma<<<GG, 256>>>(hH, hL, wH, wL, raw);
        gnorm_pass<<<EB, 256>>>(raw, P[7], xr);

        conv_w<<<256, 256>>>(P[5], wH, wL);
        gemm_mma<<<GG, 256>>>(hH, hL, wH, wL, lf);

        if (l == 0)
            gp_ln<0><<<Bsz, 256>>>(hf, xr, lf, P[8], P[9], P[6], nullptr, inH, inL);
        else
            gp_ln<1><<<Bsz, 256>>>(hf, xr, lf, P[8], P[9], P[6], out, nullptr, nullptr);
    }
}

// round 10
// speedup vs baseline: 3.6940x; 1.0811x over previous
#include <cuda_runtime.h>
#include <cuda_bf16.h>
#include <cstdint>
#include <cstddef>

#define DEVI __device__ __forceinline__
typedef __nv_bfloat16 bf16;

constexpr int Bsz = 8192, Csz = 256, NBl = 8;
constexpr size_t BC = (size_t)Bsz * Csz;   // elems per blade plane

// ---------------- scratch (device globals) ----------------
__device__ float g_raw[NBl * BC];
__device__ float g_xr [NBl * BC];
__device__ float g_lf [NBl * BC];
__device__ bf16  g_inH[NBl * BC];
__device__ bf16  g_inL[NBl * BC];
__device__ bf16  g_hH [NBl * BC];
__device__ bf16  g_hL [NBl * BC];
__device__ bf16  g_wH [4 * Csz * Csz];
__device__ bf16  g_wL [4 * Csz * Csz];

// ---------------- algebra tables ----------------
__device__ constexpr int ORD [8] = {0, 1, 2, 4, 3, 5, 6, 7};
__device__ constexpr int IDXM[8] = {0, 1, 2, 4, 3, 5, 6, 7};
__device__ constexpr int GRc [8] = {0, 1, 1, 1, 2, 2, 2, 3};
__device__ constexpr unsigned NEGM[8] = {0x00u, 0x00u, 0xAAu, 0xAAu,
                                         0x66u, 0x66u, 0xCCu, 0xCCu};
__device__ constexpr signed char PATHT[4][4][4] = {
  { { 0,-1,-1,-1}, {-1, 1,-1,-1}, {-1,-1, 2,-1}, {-1,-1,-1, 3} },
  { {-1, 4,-1,-1}, { 5,-1, 6,-1}, {-1, 7,-1, 8}, {-1,-1, 9,-1} },
  { {-1,-1,10,-1}, {-1,11,-1,12}, {13,-1,14,-1}, {-1,15,-1,-1} },
  { {-1,-1,-1,16}, {-1,-1,17,-1}, {-1,18,-1,-1}, {19,-1,-1,-1} }
};

DEVI float sigm(float x) { return 1.0f / (1.0f + __expf(-x)); }

DEVI uint32_t smem_u32(const void* p) {
    uint32_t a;
    asm("{ .reg .u64 t; cvta.to.shared.u64 t, %1; cvt.u32.u64 %0, t; }" : "=r"(a) : "l"(p));
    return a;
}

// ---- warp MMA primitives (sm_80+, valid on compute_100) ----
DEVI void ldsm_x4(uint32_t& r0, uint32_t& r1, uint32_t& r2, uint32_t& r3, uint32_t addr) {
    asm volatile("ldmatrix.sync.aligned.m8n8.x4.shared.b16 {%0,%1,%2,%3}, [%4];"
                 : "=r"(r0), "=r"(r1), "=r"(r2), "=r"(r3) : "r"(addr));
}
DEVI void mma_bf16(float* c, uint32_t a0, uint32_t a1, uint32_t a2, uint32_t a3,
                   uint32_t b0, uint32_t b1) {
    asm volatile(
        "mma.sync.aligned.m16n8k16.row.col.f32.bf16.bf16.f32 "
        "{%0,%1,%2,%3}, {%4,%5,%6,%7}, {%8,%9}, {%0,%1,%2,%3};"
        : "+f"(c[0]), "+f"(c[1]), "+f"(c[2]), "+f"(c[3])
        : "r"(a0), "r"(a1), "r"(a2), "r"(a3), "r"(b0), "r"(b1));
}
DEVI void cpa16(uint32_t dst, const void* src) {
    asm volatile("cp.async.cg.shared.global [%0], [%1], 16;" :: "r"(dst), "l"(src));
}
#define CPA_COMMIT()  asm volatile("cp.async.commit_group;" ::: "memory")
#define CPA_WAIT(n)   asm volatile("cp.async.wait_group %0;" :: "n"(n) : "memory")

// ---------------- mma.sync blade-plane GEMM (cp.async double-buffered) ----------------
// OUT[blade][b][o] = sum_i IN[blade][b][i] * W[grade(blade)][o][i]
// 3-term hi/lo split, fp32 accum: AH*WH + AL*WH + AH*WL
constexpr int SKW = 40;                    // smem row stride bf16 (32 data + 8 pad)
constexpr int ARR = 128 * SKW;             // 5120 elems per array
constexpr int STG = 4 * ARR;               // 4 arrays (AH,AL,BH,BL) per stage
constexpr int GEMM_SMEM = 2 * STG * (int)sizeof(bf16);   // 81920 B

__global__ void __launch_bounds__(256, 2)
gemm_mma(const bf16* __restrict__ AH, const bf16* __restrict__ AL,
         const bf16* __restrict__ WH, const bf16* __restrict__ WL,
         float* __restrict__ OUT)
{
    extern __shared__ bf16 smem[];
    const uint32_t sb = smem_u32(smem);

    const int tid = threadIdx.x, wid = tid >> 5, lane = tid & 31;
    const int blade = blockIdx.z, grade = GRc[blade];
    const int row0 = blockIdx.x * 128, col0 = blockIdx.y * 128;
    const int wm = wid & 1, wn = wid >> 1;     // warp tile: m64 x n32

    const bf16* aH = AH + (size_t)blade * BC + (size_t)row0 * Csz;
    const bf16* aL = AL + (size_t)blade * BC + (size_t)row0 * Csz;
    const bf16* wHp = WH + (size_t)grade * Csz * Csz + (size_t)col0 * Csz;
    const bf16* wLp = WL + (size_t)grade * Csz * Csz + (size_t)col0 * Csz;

    float acc[4][4][4];
#pragma unroll
    for (int mi = 0; mi < 4; mi++)
#pragma unroll
        for (int ni = 0; ni < 4; ni++)
#pragma unroll
            for (int q = 0; q < 4; q++) acc[mi][ni][q] = 0.0f;

    // per-lane ldmatrix offsets (bytes) within a k16 step
    const int lq = lane >> 3, lr = lane & 7;
    const uint32_t offA = (uint32_t)(((lq & 1) * 8 + lr) * SKW + (lq >> 1) * 8) * 2;
    const uint32_t offB = (uint32_t)(((lq >> 1) * 8 + lr) * SKW + (lq & 1) * 8) * 2;

    // issue async loads of chunk ch into stage s
    auto load_chunk = [&](int ch, int s) {
        const uint32_t base = sb + (uint32_t)(s * STG) * 2;
#pragma unroll
        for (int it = 0; it < 2; it++) {
            const int t = tid + it * 256;
            const int r = t >> 2, c = t & 3;
            const size_t src = (size_t)r * Csz + ch * 32 + c * 8;
            const uint32_t d = (uint32_t)(r * SKW + c * 8) * 2;
            cpa16(base + 0 * ARR * 2 + d, aH  + src);
            cpa16(base + 1 * ARR * 2 + d, aL  + src);
            cpa16(base + 2 * ARR * 2 + d, wHp + src);
            cpa16(base + 3 * ARR * 2 + d, wLp + src);
        }
        CPA_COMMIT();
    };

    load_chunk(0, 0);

    for (int ch = 0; ch < 8; ch++) {
        const int s = ch & 1;
        if (ch + 1 < 8) {
            load_chunk(ch + 1, (ch + 1) & 1);
            CPA_WAIT(1);          // chunk ch complete, ch+1 in flight
        } else {
            CPA_WAIT(0);
        }
        __syncthreads();

        const uint32_t bAH = sb + (uint32_t)(s * STG + 0 * ARR) * 2;
        const uint32_t bAL = sb + (uint32_t)(s * STG + 1 * ARR) * 2;
        const uint32_t bBH = sb + (uint32_t)(s * STG + 2 * ARR) * 2;
        const uint32_t bBL = sb + (uint32_t)(s * STG + 3 * ARR) * 2;

#pragma unroll
        for (int kh = 0; kh < 2; kh++) {
            const uint32_t kb = (uint32_t)(kh * 16) * 2;
            uint32_t bh[4][2], bl[4][2];
#pragma unroll
            for (int nb = 0; nb < 2; nb++) {
                const uint32_t nbase = (uint32_t)((wn * 32 + nb * 16) * SKW) * 2;
                ldsm_x4(bh[nb*2][0], bh[nb*2][1], bh[nb*2+1][0], bh[nb*2+1][1],
                        bBH + nbase + offB + kb);
                ldsm_x4(bl[nb*2][0], bl[nb*2][1], bl[nb*2+1][0], bl[nb*2+1][1],
                        bBL + nbase + offB + kb);
            }
#pragma unroll
            for (int mi = 0; mi < 4; mi++) {
                const uint32_t mbase = (uint32_t)((wm * 64 + mi * 16) * SKW) * 2;
                uint32_t ah0, ah1, ah2, ah3, al0, al1, al2, al3;
                ldsm_x4(ah0, ah1, ah2, ah3, bAH + mbase + offA + kb);
                ldsm_x4(al0, al1, al2, al3, bAL + mbase + offA + kb);
#pragma unroll
                for (int ni = 0; ni < 4; ni++) {
                    mma_bf16(acc[mi][ni], ah0, ah1, ah2, ah3, bh[ni][0], bh[ni][1]);
                    mma_bf16(acc[mi][ni], al0, al1, al2, al3, bh[ni][0], bh[ni][1]);
                    mma_bf16(acc[mi][ni], ah0, ah1, ah2, ah3, bl[ni][0], bl[ni][1]);
                }
            }
        }
        __syncthreads();          // stage s free for reuse (loaded at ch+2)
    }

    // epilogue: write fp32 planar
    float* outp = OUT + (size_t)blade * BC;
#pragma unroll
    for (int mi = 0; mi < 4; mi++) {
        const int m0 = row0 + wm * 64 + mi * 16 + (lane >> 2);
#pragma unroll
        for (int ni = 0; ni < 4; ni++) {
            const int n = col0 + wn * 32 + ni * 8 + (lane & 3) * 2;
            *(float2*)(outp + (size_t)m0 * Csz + n)       = make_float2(acc[mi][ni][0], acc[mi][ni][1]);
            *(float2*)(outp + (size_t)(m0 + 8) * Csz + n) = make_float2(acc[mi][ni][2], acc[mi][ni][3]);
        }
    }
}

// ---------------- conversions & elementwise passes ----------------
__global__ void conv_x(const float* __restrict__ X, bf16* __restrict__ H, bf16* __restrict__ L) {
    const size_t idx = (size_t)blockIdx.x * 256 + threadIdx.x;
    const float4 a = *(const float4*)(X + idx * 8);
    const float4 b = *(const float4*)(X + idx * 8 + 4);
    const float v[8] = {a.x, a.y, a.z, a.w, b.x, b.y, b.z, b.w};
#pragma unroll
    for (int k = 0; k < 8; k++) {
        const bf16 h = __float2bfloat16(v[k]);
        H[k * BC + idx] = h;
        L[k * BC + idx] = __float2bfloat16(v[k] - __bfloat162float(h));
    }
}

__global__ void conv_w(const float* __restrict__ W, bf16* __restrict__ WH, bf16* __restrict__ WL) {
    const int idx = blockIdx.x * 256 + threadIdx.x;  // o*256+i
    const float4 v = *(const float4*)(W + (size_t)idx * 4);
    const float g[4] = {v.x, v.y, v.z, v.w};
#pragma unroll
    for (int gg = 0; gg < 4; gg++) {
        const bf16 h = __float2bfloat16(g[gg]);
        WH[gg * 65536 + idx] = h;
        WL[gg * 65536 + idx] = __float2bfloat16(g[gg] - __bfloat162float(h));
    }
}

__global__ void silu_pass(const float* __restrict__ RAW, const float* __restrict__ blin,
                          const float* __restrict__ pa, const float* __restrict__ pb,
                          bf16* __restrict__ HH, bf16* __restrict__ HL) {
    const size_t idx = (size_t)blockIdx.x * 256 + threadIdx.x;
    const int c = (int)(idx & 255);
    float y[8];
#pragma unroll
    for (int k = 0; k < 8; k++) y[k] = RAW[k * BC + idx];
    y[0] += blin[c];
    const float i0 = y[0];
    const float i1 = y[1]*y[1] + y[2]*y[2] + y[3]*y[3];
    const float i2 = y[4]*y[4] + y[5]*y[5] + y[6]*y[6];
    const float i3 = y[7]*y[7];
    const float g0 = sigm(pa[c*4+0] * i0 + pb[c*4+0]);
    const float g1 = sigm(pa[c*4+1] * i1 + pb[c*4+1]);
    const float g2 = sigm(pa[c*4+2] * i2 + pb[c*4+2]);
    const float g3 = sigm(pa[c*4+3] * i3 + pb[c*4+3]);
    const float gk[8] = {g0, g1, g1, g1, g2, g2, g2, g3};
#pragma unroll
    for (int k = 0; k < 8; k++) {
        const float v = y[k] * gk[k];
        const bf16 h = __float2bfloat16(v);
        HH[k * BC + idx] = h;
        HL[k * BC + idx] = __float2bfloat16(v - __bfloat162float(h));
    }
}

__global__ void gnorm_pass(const float* __restrict__ RAW, const float* __restrict__ pa,
                           float* __restrict__ XR) {
    const size_t idx = (size_t)blockIdx.x * 256 + threadIdx.x;
    const int c = (int)(idx & 255);
    float y[8];
#pragma unroll
    for (int k = 0; k < 8; k++) y[k] = RAW[k * BC + idx];
    const float n0 = fabsf(y[0]);
    const float n1 = sqrtf(y[1]*y[1] + y[2]*y[2] + y[3]*y[3]);
    const float n2 = sqrtf(y[4]*y[4] + y[5]*y[5] + y[6]*y[6]);
    const float n3 = fabsf(y[7]);
    const float r0 = 1.0f / (fmaf(sigm(pa[c*4+0]), n0 - 1.0f, 1.0f) + 1e-6f);
    const float r1 = 1.0f / (fmaf(sigm(pa[c*4+1]), n1 - 1.0f, 1.0f) + 1e-6f);
    const float r2 = 1.0f / (fmaf(sigm(pa[c*4+2]), n2 - 1.0f, 1.0f) + 1e-6f);
    const float r3 = 1.0f / (fmaf(sigm(pa[c*4+3]), n3 - 1.0f, 1.0f) + 1e-6f);
    const float rk[8] = {r0, r1, r1, r1, r2, r2, r2, r3};
#pragma unroll
    for (int k = 0; k < 8; k++) XR[k * BC + idx] = y[k] * rk[k];
}

// ---------------- fused geometric product + layernorm ----------------
// x reconstructed from hi+lo planes (exact to 2^-16)
template <int OUTMODE>
__global__ void __launch_bounds__(256, 4)
gp_ln(const bf16* __restrict__ XhH, const bf16* __restrict__ XhL,
      const float* __restrict__ XR, const float* __restrict__ Lf,
      const float* __restrict__ GPW, const float* __restrict__ LNA,
      const float* __restrict__ BL,
      float* __restrict__ OutF, bf16* __restrict__ OutH, bf16* __restrict__ OutL)
{
    const int b = blockIdx.x, c = threadIdx.x;
    const size_t idx = (size_t)b * Csz + c;

    float xv[8], rv[8], lv[8];
#pragma unroll
    for (int k = 0; k < 8; k++) {
        xv[k] = __bfloat162float(XhH[k * BC + idx]) + __bfloat162float(XhL[k * BC + idx]);
        rv[k] = XR[k * BC + idx];
        lv[k] = Lf[k * BC + idx];
    }
    lv[0] += BL[c];

    float w20[20];
    {
        const float* wp = GPW + c * 20;
#pragma unroll
        for (int q = 0; q < 5; q++) *(float4*)&w20[q*4] = *(const float4*)(wp + q*4);
    }

    float gp[8] = {0,0,0,0,0,0,0,0};
#pragma unroll
    for (int i = 0; i < 8; i++) {
#pragma unroll
        for (int j = 0; j < 8; j++) {
            const int ma = ORD[i], mb = ORD[j];
            const int ko = IDXM[ma ^ mb];
            const int p  = PATHT[GRc[i]][GRc[j]][GRc[ko]];
            const bool neg = (NEGM[ma] >> mb) & 1;
            const float wv = neg ? -w20[p] : w20[p];
            gp[ko] = fmaf(wv, xv[i] * rv[j], gp[ko]);
        }
    }

    float s[8], sq = 0.0f;
#pragma unroll
    for (int k = 0; k < 8; k++) {
        s[k] = (lv[k] + gp[k]) * 0.70710678118654752f;
        sq = fmaf(s[k], s[k], sq);
    }
    float v = sqrtf(sq);

    __shared__ float red[8];
#pragma unroll
    for (int off = 16; off; off >>= 1) v += __shfl_xor_sync(0xffffffffu, v, off);
    if ((c & 31) == 0) red[c >> 5] = v;
    __syncthreads();
    const float tot = red[0]+red[1]+red[2]+red[3]+red[4]+red[5]+red[6]+red[7];
    const float scale = LNA[c] / (tot * (1.0f / 256.0f) + 1e-6f);

    if constexpr (OUTMODE == 0) {
#pragma unroll
        for (int k = 0; k < 8; k++) {
            const float sv = s[k] * scale;
            const bf16 h = __float2bfloat16(sv);
            OutH[k * BC + idx] = h;
            OutL[k * BC + idx] = __float2bfloat16(sv - __bfloat162float(h));
        }
    } else {
        float4* dst = (float4*)(OutF + idx * 8);
        dst[0] = make_float4(s[0]*scale, s[1]*scale, s[2]*scale, s[3]*scale);
        dst[1] = make_float4(s[4]*scale, s[5]*scale, s[6]*scale, s[7]*scale);
    }
}

// ---------------- launch ----------------
extern "C" void kernel_launch(void* const* d_in, const int* in_sizes, int n_in,
                              void* d_out, int out_size)
{
    (void)in_sizes; (void)n_in; (void)out_size;
    const float* x = (const float*)d_in[0];
    float* out = (float*)d_out;

    cudaFuncSetAttribute(gemm_mma, cudaFuncAttributeMaxDynamicSharedMemorySize, GEMM_SMEM);

    float *raw, *xr, *lf;
    bf16 *inH, *inL, *hH, *hL, *wH, *wL;
    cudaGetSymbolAddress((void**)&raw, g_raw);
    cudaGetSymbolAddress((void**)&xr,  g_xr);
    cudaGetSymbolAddress((void**)&lf,  g_lf);
    cudaGetSymbolAddress((void**)&inH, g_inH);
    cudaGetSymbolAddress((void**)&inL, g_inL);
    cudaGetSymbolAddress((void**)&hH,  g_hH);
    cudaGetSymbolAddress((void**)&hL,  g_hL);
    cudaGetSymbolAddress((void**)&wH,  g_wH);
    cudaGetSymbolAddress((void**)&wL,  g_wL);

    const int EB = (int)(BC / 256);
    const dim3 GG(Bsz / 128, Csz / 128, NBl);   // 64 x 2 x 8

    conv_x<<<EB, 256>>>(x, inH, inL);

    for (int l = 0; l < 2; l++) {
        const float* const* P = (const float* const*)(d_in + 1 + 10 * l);
        // P: [w_lin, b_lin, silu_a, silu_b, w_right, w_left, b_left, norm_a, gp_w, ln_a]
        conv_w<<<256, 256>>>(P[0], wH, wL);
        gemm_mma<<<GG, 256, GEMM_SMEM>>>(inH, inL, wH, wL, raw);
        silu_pass<<<EB, 256>>>(raw, P[1], P[2], P[3], hH, hL);

        conv_w<<<256, 256>>>(P[4], wH, wL);
        gemm_mma<<<GG, 256, GEMM_SMEM>>>(hH, hL, wH, wL, raw);
        gnorm_pass<<<EB, 256>>>(raw, P[7], xr);

        conv_w<<<256, 256>>>(P[5], wH, wL);
        gemm_mma<<<GG, 256, GEMM_SMEM>>>(hH, hL, wH, wL, lf);

        if (l == 0)
            gp_ln<0><<<Bsz, 256>>>(hH, hL, xr, lf, P[8], P[9], P[6], nullptr, inH, inL);
        else
            gp_ln<1><<<Bsz, 256>>>(hH, hL, xr, lf, P[8], P[9], P[6], out, nullptr, nullptr);
    }
}

// round 11
// speedup vs baseline: 4.5266x; 1.2254x over previous
#include <cuda_runtime.h>
#include <cuda_fp16.h>
#include <cstdint>
#include <cstddef>

#define DEVI __device__ __forceinline__
typedef __half f16;

constexpr int Bsz = 8192, Csz = 256, NBl = 8;
constexpr size_t BC = (size_t)Bsz * Csz;   // elems per blade plane

// ---------------- scratch (device globals) ----------------
__device__ float g_raw[NBl * BC];
__device__ float g_xr [NBl * BC];
__device__ float g_lf [NBl * BC];
__device__ f16   g_inH[NBl * BC];
__device__ f16   g_inL[NBl * BC];
__device__ f16   g_hH [NBl * BC];
__device__ f16   g_hL [NBl * BC];
__device__ f16   g_wH [4 * Csz * Csz];
__device__ f16   g_wL [4 * Csz * Csz];

// ---------------- algebra tables ----------------
__device__ constexpr int ORD [8] = {0, 1, 2, 4, 3, 5, 6, 7};
__device__ constexpr int IDXM[8] = {0, 1, 2, 4, 3, 5, 6, 7};
__device__ constexpr int GRc [8] = {0, 1, 1, 1, 2, 2, 2, 3};
__device__ constexpr unsigned NEGM[8] = {0x00u, 0x00u, 0xAAu, 0xAAu,
                                         0x66u, 0x66u, 0xCCu, 0xCCu};
__device__ constexpr signed char PATHT[4][4][4] = {
  { { 0,-1,-1,-1}, {-1, 1,-1,-1}, {-1,-1, 2,-1}, {-1,-1,-1, 3} },
  { {-1, 4,-1,-1}, { 5,-1, 6,-1}, {-1, 7,-1, 8}, {-1,-1, 9,-1} },
  { {-1,-1,10,-1}, {-1,11,-1,12}, {13,-1,14,-1}, {-1,15,-1,-1} },
  { {-1,-1,-1,16}, {-1,-1,17,-1}, {-1,18,-1,-1}, {19,-1,-1,-1} }
};

DEVI float sigm(float x) { return 1.0f / (1.0f + __expf(-x)); }

DEVI uint32_t smem_u32(const void* p) {
    uint32_t a;
    asm("{ .reg .u64 t; cvta.to.shared.u64 t, %1; cvt.u32.u64 %0, t; }" : "=r"(a) : "l"(p));
    return a;
}

// ---- warp MMA primitives (sm_80+, valid on compute_100) ----
DEVI void ldsm_x4(uint32_t& r0, uint32_t& r1, uint32_t& r2, uint32_t& r3, uint32_t addr) {
    asm volatile("ldmatrix.sync.aligned.m8n8.x4.shared.b16 {%0,%1,%2,%3}, [%4];"
                 : "=r"(r0), "=r"(r1), "=r"(r2), "=r"(r3) : "r"(addr));
}
DEVI void mma_f16(float* c, uint32_t a0, uint32_t a1, uint32_t a2, uint32_t a3,
                  uint32_t b0, uint32_t b1) {
    asm volatile(
        "mma.sync.aligned.m16n8k16.row.col.f32.f16.f16.f32 "
        "{%0,%1,%2,%3}, {%4,%5,%6,%7}, {%8,%9}, {%0,%1,%2,%3};"
        : "+f"(c[0]), "+f"(c[1]), "+f"(c[2]), "+f"(c[3])
        : "r"(a0), "r"(a1), "r"(a2), "r"(a3), "r"(b0), "r"(b1));
}
DEVI void cpa16(uint32_t dst, const void* src) {
    asm volatile("cp.async.cg.shared.global [%0], [%1], 16;" :: "r"(dst), "l"(src));
}
#define CPA_COMMIT()  asm volatile("cp.async.commit_group;" ::: "memory")
#define CPA_WAIT(n)   asm volatile("cp.async.wait_group %0;" :: "n"(n) : "memory")

// ---------------- mma.sync blade-plane GEMM (fp16 2-term, cp.async 2-stage) ----------------
// OUT[blade][b][o] = sum_i A[blade][b][i] * (WH+WL)[grade(blade)][o][i]
// A rounded to fp16 once; W split exactly into fp16 hi+lo. 2 MMA terms.
constexpr int SKW = 40;                    // smem row stride (32 data + 8 pad)
constexpr int ARR = 128 * SKW;             // elems per array
constexpr int STG = 3 * ARR;               // A, WH, WL per stage
constexpr int GEMM_SMEM = 2 * STG * (int)sizeof(f16);   // 61440 B

__global__ void __launch_bounds__(256, 2)
gemm_mma(const f16* __restrict__ A, const f16* __restrict__ WH,
         const f16* __restrict__ WL, float* __restrict__ OUT)
{
    extern __shared__ f16 smem[];
    const uint32_t sb = smem_u32(smem);

    const int tid = threadIdx.x, wid = tid >> 5, lane = tid & 31;
    const int blade = blockIdx.z, grade = GRc[blade];
    const int row0 = blockIdx.x * 128, col0 = blockIdx.y * 128;
    const int wm = wid & 1, wn = wid >> 1;     // warp tile: m64 x n32

    const f16* aP  = A  + (size_t)blade * BC + (size_t)row0 * Csz;
    const f16* wHp = WH + (size_t)grade * Csz * Csz + (size_t)col0 * Csz;
    const f16* wLp = WL + (size_t)grade * Csz * Csz + (size_t)col0 * Csz;

    float acc[4][4][4];
#pragma unroll
    for (int mi = 0; mi < 4; mi++)
#pragma unroll
        for (int ni = 0; ni < 4; ni++)
#pragma unroll
            for (int q = 0; q < 4; q++) acc[mi][ni][q] = 0.0f;

    const int lq = lane >> 3, lr = lane & 7;
    const uint32_t offA = (uint32_t)(((lq & 1) * 8 + lr) * SKW + (lq >> 1) * 8) * 2;
    const uint32_t offB = (uint32_t)(((lq >> 1) * 8 + lr) * SKW + (lq & 1) * 8) * 2;

    auto load_chunk = [&](int ch, int s) {
        const uint32_t base = sb + (uint32_t)(s * STG) * 2;
#pragma unroll
        for (int it = 0; it < 2; it++) {
            const int t = tid + it * 256;
            const int r = t >> 2, c = t & 3;
            const size_t src = (size_t)r * Csz + ch * 32 + c * 8;
            const uint32_t d = (uint32_t)(r * SKW + c * 8) * 2;
            cpa16(base + 0 * ARR * 2 + d, aP  + src);
            cpa16(base + 1 * ARR * 2 + d, wHp + src);
            cpa16(base + 2 * ARR * 2 + d, wLp + src);
        }
        CPA_COMMIT();
    };

    load_chunk(0, 0);

    for (int ch = 0; ch < 8; ch++) {
        const int s = ch & 1;
        if (ch + 1 < 8) {
            load_chunk(ch + 1, (ch + 1) & 1);
            CPA_WAIT(1);
        } else {
            CPA_WAIT(0);
        }
        __syncthreads();

        const uint32_t bA  = sb + (uint32_t)(s * STG + 0 * ARR) * 2;
        const uint32_t bBH = sb + (uint32_t)(s * STG + 1 * ARR) * 2;
        const uint32_t bBL = sb + (uint32_t)(s * STG + 2 * ARR) * 2;

#pragma unroll
        for (int kh = 0; kh < 2; kh++) {
            const uint32_t kb = (uint32_t)(kh * 16) * 2;
            uint32_t bh[4][2], bl[4][2];
#pragma unroll
            for (int nb = 0; nb < 2; nb++) {
                const uint32_t nbase = (uint32_t)((wn * 32 + nb * 16) * SKW) * 2;
                ldsm_x4(bh[nb*2][0], bh[nb*2][1], bh[nb*2+1][0], bh[nb*2+1][1],
                        bBH + nbase + offB + kb);
                ldsm_x4(bl[nb*2][0], bl[nb*2][1], bl[nb*2+1][0], bl[nb*2+1][1],
                        bBL + nbase + offB + kb);
            }
#pragma unroll
            for (int mi = 0; mi < 4; mi++) {
                const uint32_t mbase = (uint32_t)((wm * 64 + mi * 16) * SKW) * 2;
                uint32_t a0, a1, a2, a3;
                ldsm_x4(a0, a1, a2, a3, bA + mbase + offA + kb);
#pragma unroll
                for (int ni = 0; ni < 4; ni++) {
                    mma_f16(acc[mi][ni], a0, a1, a2, a3, bh[ni][0], bh[ni][1]);
                    mma_f16(acc[mi][ni], a0, a1, a2, a3, bl[ni][0], bl[ni][1]);
                }
            }
        }
        __syncthreads();
    }

    float* outp = OUT + (size_t)blade * BC;
#pragma unroll
    for (int mi = 0; mi < 4; mi++) {
        const int m0 = row0 + wm * 64 + mi * 16 + (lane >> 2);
#pragma unroll
        for (int ni = 0; ni < 4; ni++) {
            const int n = col0 + wn * 32 + ni * 8 + (lane & 3) * 2;
            *(float2*)(outp + (size_t)m0 * Csz + n)       = make_float2(acc[mi][ni][0], acc[mi][ni][1]);
            *(float2*)(outp + (size_t)(m0 + 8) * Csz + n) = make_float2(acc[mi][ni][2], acc[mi][ni][3]);
        }
    }
}

// ---------------- conversions & elementwise passes ----------------
__global__ void conv_x(const float* __restrict__ X, f16* __restrict__ H, f16* __restrict__ L) {
    const size_t idx = (size_t)blockIdx.x * 256 + threadIdx.x;
    const float4 a = *(const float4*)(X + idx * 8);
    const float4 b = *(const float4*)(X + idx * 8 + 4);
    const float v[8] = {a.x, a.y, a.z, a.w, b.x, b.y, b.z, b.w};
#pragma unroll
    for (int k = 0; k < 8; k++) {
        const f16 h = __float2half_rn(v[k]);
        H[k * BC + idx] = h;
        L[k * BC + idx] = __float2half_rn(v[k] - __half2float(h));
    }
}

__global__ void conv_w(const float* __restrict__ W, f16* __restrict__ WH, f16* __restrict__ WL) {
    const int idx = blockIdx.x * 256 + threadIdx.x;  // o*256+i
    const float4 v = *(const float4*)(W + (size_t)idx * 4);
    const float g[4] = {v.x, v.y, v.z, v.w};
#pragma unroll
    for (int gg = 0; gg < 4; gg++) {
        const f16 h = __float2half_rn(g[gg]);
        WH[gg * 65536 + idx] = h;
        WL[gg * 65536 + idx] = __float2half_rn(g[gg] - __half2float(h));
    }
}

__global__ void silu_pass(const float* __restrict__ RAW, const float* __restrict__ blin,
                          const float* __restrict__ pa, const float* __restrict__ pb,
                          f16* __restrict__ HH, f16* __restrict__ HL) {
    const size_t idx = (size_t)blockIdx.x * 256 + threadIdx.x;
    const int c = (int)(idx & 255);
    float y[8];
#pragma unroll
    for (int k = 0; k < 8; k++) y[k] = RAW[k * BC + idx];
    y[0] += blin[c];
    const float i0 = y[0];
    const float i1 = y[1]*y[1] + y[2]*y[2] + y[3]*y[3];
    const float i2 = y[4]*y[4] + y[5]*y[5] + y[6]*y[6];
    const float i3 = y[7]*y[7];
    const float g0 = sigm(pa[c*4+0] * i0 + pb[c*4+0]);
    const float g1 = sigm(pa[c*4+1] * i1 + pb[c*4+1]);
    const float g2 = sigm(pa[c*4+2] * i2 + pb[c*4+2]);
    const float g3 = sigm(pa[c*4+3] * i3 + pb[c*4+3]);
    const float gk[8] = {g0, g1, g1, g1, g2, g2, g2, g3};
#pragma unroll
    for (int k = 0; k < 8; k++) {
        const float v = y[k] * gk[k];
        const f16 h = __float2half_rn(v);
        HH[k * BC + idx] = h;
        HL[k * BC + idx] = __float2half_rn(v - __half2float(h));
    }
}

__global__ void gnorm_pass(const float* __restrict__ RAW, const float* __restrict__ pa,
                           float* __restrict__ XR) {
    const size_t idx = (size_t)blockIdx.x * 256 + threadIdx.x;
    const int c = (int)(idx & 255);
    float y[8];
#pragma unroll
    for (int k = 0; k < 8; k++) y[k] = RAW[k * BC + idx];
    const float n0 = fabsf(y[0]);
    const float n1 = sqrtf(y[1]*y[1] + y[2]*y[2] + y[3]*y[3]);
    const float n2 = sqrtf(y[4]*y[4] + y[5]*y[5] + y[6]*y[6]);
    const float n3 = fabsf(y[7]);
    const float r0 = 1.0f / (fmaf(sigm(pa[c*4+0]), n0 - 1.0f, 1.0f) + 1e-6f);
    const float r1 = 1.0f / (fmaf(sigm(pa[c*4+1]), n1 - 1.0f, 1.0f) + 1e-6f);
    const float r2 = 1.0f / (fmaf(sigm(pa[c*4+2]), n2 - 1.0f, 1.0f) + 1e-6f);
    const float r3 = 1.0f / (fmaf(sigm(pa[c*4+3]), n3 - 1.0f, 1.0f) + 1e-6f);
    const float rk[8] = {r0, r1, r1, r1, r2, r2, r2, r3};
#pragma unroll
    for (int k = 0; k < 8; k++) XR[k * BC + idx] = y[k] * rk[k];
}

// ---------------- fused geometric product + layernorm ----------------
// x reconstructed from fp16 hi+lo (exact to ~2^-22)
template <int OUTMODE>
__global__ void __launch_bounds__(256, 4)
gp_ln(const f16* __restrict__ XhH, const f16* __restrict__ XhL,
      const float* __restrict__ XR, const float* __restrict__ Lf,
      const float* __restrict__ GPW, const float* __restrict__ LNA,
      const float* __restrict__ BL,
      float* __restrict__ OutF, f16* __restrict__ OutH, f16* __restrict__ OutL)
{
    const int b = blockIdx.x, c = threadIdx.x;
    const size_t idx = (size_t)b * Csz + c;

    float xv[8], rv[8], lv[8];
#pragma unroll
    for (int k = 0; k < 8; k++) {
        xv[k] = __half2float(XhH[k * BC + idx]) + __half2float(XhL[k * BC + idx]);
        rv[k] = XR[k * BC + idx];
        lv[k] = Lf[k * BC + idx];
    }
    lv[0] += BL[c];

    float w20[20];
    {
        const float* wp = GPW + c * 20;
#pragma unroll
        for (int q = 0; q < 5; q++) *(float4*)&w20[q*4] = *(const float4*)(wp + q*4);
    }

    float gp[8] = {0,0,0,0,0,0,0,0};
#pragma unroll
    for (int i = 0; i < 8; i++) {
#pragma unroll
        for (int j = 0; j < 8; j++) {
            const int ma = ORD[i], mb = ORD[j];
            const int ko = IDXM[ma ^ mb];
            const int p  = PATHT[GRc[i]][GRc[j]][GRc[ko]];
            const bool neg = (NEGM[ma] >> mb) & 1;
            const float wv = neg ? -w20[p] : w20[p];
            gp[ko] = fmaf(wv, xv[i] * rv[j], gp[ko]);
        }
    }

    float s[8], sq = 0.0f;
#pragma unroll
    for (int k = 0; k < 8; k++) {
        s[k] = (lv[k] + gp[k]) * 0.70710678118654752f;
        sq = fmaf(s[k], s[k], sq);
    }
    float v = sqrtf(sq);

    __shared__ float red[8];
#pragma unroll
    for (int off = 16; off; off >>= 1) v += __shfl_xor_sync(0xffffffffu, v, off);
    if ((c & 31) == 0) red[c >> 5] = v;
    __syncthreads();
    const float tot = red[0]+red[1]+red[2]+red[3]+red[4]+red[5]+red[6]+red[7];
    const float scale = LNA[c] / (tot * (1.0f / 256.0f) + 1e-6f);

    if constexpr (OUTMODE == 0) {
#pragma unroll
        for (int k = 0; k < 8; k++) {
            const float sv = s[k] * scale;
            const f16 h = __float2half_rn(sv);
            OutH[k * BC + idx] = h;
            OutL[k * BC + idx] = __float2half_rn(sv - __half2float(h));
        }
    } else {
        float4* dst = (float4*)(OutF + idx * 8);
        dst[0] = make_float4(s[0]*scale, s[1]*scale, s[2]*scale, s[3]*scale);
        dst[1] = make_float4(s[4]*scale, s[5]*scale, s[6]*scale, s[7]*scale);
    }
}

// ---------------- launch ----------------
extern "C" void kernel_launch(void* const* d_in, const int* in_sizes, int n_in,
                              void* d_out, int out_size)
{
    (void)in_sizes; (void)n_in; (void)out_size;
    const float* x = (const float*)d_in[0];
    float* out = (float*)d_out;

    cudaFuncSetAttribute(gemm_mma, cudaFuncAttributeMaxDynamicSharedMemorySize, GEMM_SMEM);

    float *raw, *xr, *lf;
    f16 *inH, *inL, *hH, *hL, *wH, *wL;
    cudaGetSymbolAddress((void**)&raw, g_raw);
    cudaGetSymbolAddress((void**)&xr,  g_xr);
    cudaGetSymbolAddress((void**)&lf,  g_lf);
    cudaGetSymbolAddress((void**)&inH, g_inH);
    cudaGetSymbolAddress((void**)&inL, g_inL);
    cudaGetSymbolAddress((void**)&hH,  g_hH);
    cudaGetSymbolAddress((void**)&hL,  g_hL);
    cudaGetSymbolAddress((void**)&wH,  g_wH);
    cudaGetSymbolAddress((void**)&wL,  g_wL);

    const int EB = (int)(BC / 256);
    const dim3 GG(Bsz / 128, Csz / 128, NBl);   // 64 x 2 x 8

    conv_x<<<EB, 256>>>(x, inH, inL);

    for (int l = 0; l < 2; l++) {
        const float* const* P = (const float* const*)(d_in + 1 + 10 * l);
        // P: [w_lin, b_lin, silu_a, silu_b, w_right, w_left, b_left, norm_a, gp_w, ln_a]
        conv_w<<<256, 256>>>(P[0], wH, wL);
        gemm_mma<<<GG, 256, GEMM_SMEM>>>(inH, wH, wL, raw);
        silu_pass<<<EB, 256>>>(raw, P[1], P[2], P[3], hH, hL);

        conv_w<<<256, 256>>>(P[4], wH, wL);
        gemm_mma<<<GG, 256, GEMM_SMEM>>>(hH, wH, wL, raw);
        gnorm_pass<<<EB, 256>>>(raw, P[7], xr);

        conv_w<<<256, 256>>>(P[5], wH, wL);
        gemm_mma<<<GG, 256, GEMM_SMEM>>>(hH, wH, wL, lf);

        if (l == 0)
            gp_ln<0><<<Bsz, 256>>>(hH, hL, xr, lf, P[8], P[9], P[6], nullptr, inH, inL);
        else
            gp_ln<1><<<Bsz, 256>>>(hH, hL, xr, lf, P[8], P[9], P[6], out, nullptr, nullptr);
    }
}